// round 10
// baseline (speedup 1.0000x reference)
#include <cuda_runtime.h>
#include <cstdint>

#define THRESH 0.8f
#define DECAY  0.2f

constexpr int BSZ = 256;   // batch
constexpr int CH  = 4096;  // out features
constexpr int KD  = 4096;  // in features

// Scratch: 3 planes [BSZ][CH] of fc outputs (x@Wj.T + bj), time-invariant.
__device__ float g_y3[3 * BSZ * CH];

// Split-K=2: k halves {0..2047}, {2048..4095}; each an ascending fused-FMA
// chain from zero; folded (p0 + p1); bias last. ALL planes.
__constant__ int c_bnds[4] = { 2048, 4096, 1 << 30, 1 << 30 };

// ---------------- GEMM: y[j][m][n] = sum_k x[m][k]*Wj[n][k] + bj[n] ----------
constexpr int BM = 128, BN = 64, BK = 16, TM = 8, TN = 4;  // 256 threads

__global__ __launch_bounds__(256) void gemm3_kernel(
    const float* __restrict__ x,
    const float* __restrict__ W1, const float* __restrict__ b1,
    const float* __restrict__ W2, const float* __restrict__ b2,
    const float* __restrict__ W3, const float* __restrict__ b3)
{
    __shared__ float As[BK][BM];   // [k][m]
    __shared__ float Bs[BK][BN];   // [k][n]

    const int tid = threadIdx.x;
    const int bx  = blockIdx.x;    // 0 .. 3*CH/BN - 1   (192)
    const int by  = blockIdx.y;    // 0 .. BSZ/BM - 1    (2)

    const int blocksPerJ = CH / BN;          // 64
    const int j  = bx / blocksPerJ;          // which weight matrix
    const int n0 = (bx % blocksPerJ) * BN;
    const int m0 = by * BM;

    const float* W    = (j == 0) ? W1 : (j == 1) ? W2 : W3;
    const float* bias = (j == 0) ? b1 : (j == 1) ? b2 : b3;

    const int tx = tid % (BN / TN);   // 16 -> n
    const int ty = tid / (BN / TN);   // 16 -> m

    float run[TM][TN];   // current slice accumulator (ascending fma chain)
    float tot[TM][TN];   // sequential sum of slice sums
    #pragma unroll
    for (int i = 0; i < TM; i++)
        #pragma unroll
        for (int q = 0; q < TN; q++) { run[i][q] = 0.f; tot[i][q] = 0.f; }

    int bi = 0;
    int nextB = c_bnds[0];

    const int NKB = KD / BK;   // 256 BK-blocks
    for (int kb = 0; kb < NKB; kb++) {
        const int k0 = kb * BK;
        // A tile: BM x BK = 2048 floats = 512 float4, 2 per thread
        #pragma unroll
        for (int l = 0; l < 2; l++) {
            int li  = tid + l * 256;
            int row = li >> 2;           // 0..127 (m within tile)
            int kq  = (li & 3) * 4;      // 0,4,8,12
            float4 v = *(const float4*)(x + (size_t)(m0 + row) * KD + k0 + kq);
            As[kq + 0][row] = v.x;
            As[kq + 1][row] = v.y;
            As[kq + 2][row] = v.z;
            As[kq + 3][row] = v.w;
        }
        // W tile: BN x BK = 1024 floats = 256 float4, 1 per thread
        {
            int row = tid >> 2;          // 0..63 (n within tile)
            int kq  = (tid & 3) * 4;
            float4 v = *(const float4*)(W + (size_t)(n0 + row) * KD + k0 + kq);
            Bs[kq + 0][row] = v.x;
            Bs[kq + 1][row] = v.y;
            Bs[kq + 2][row] = v.z;
            Bs[kq + 3][row] = v.w;
        }
        __syncthreads();

        #pragma unroll
        for (int kk = 0; kk < BK; kk++) {
            float a[TM], bb[TN];
            #pragma unroll
            for (int i = 0; i < TM; i++) a[i] = As[kk][ty * TM + i];
            #pragma unroll
            for (int q = 0; q < TN; q++) bb[q] = Bs[kk][tx * TN + q];
            #pragma unroll
            for (int i = 0; i < TM; i++)
                #pragma unroll
                for (int q = 0; q < TN; q++)
                    run[i][q] = __fmaf_rn(a[i], bb[q], run[i][q]);
        }

        if (k0 + 16 == nextB) {   // fold slice sum at boundary (multiples of 16)
            #pragma unroll
            for (int i = 0; i < TM; i++)
                #pragma unroll
                for (int q = 0; q < TN; q++) {
                    tot[i][q] = __fadd_rn(tot[i][q], run[i][q]);
                    run[i][q] = 0.f;
                }
            nextB = c_bnds[++bi];
        }
        __syncthreads();
    }

    float* yp = g_y3 + (size_t)j * BSZ * CH;
    #pragma unroll
    for (int i = 0; i < TM; i++) {
        int m = m0 + ty * TM + i;
        #pragma unroll
        for (int q = 0; q < TN; q++) {
            int n = n0 + tx * TN + q;
            yp[(size_t)m * CH + n] = __fadd_rn(tot[i][q], bias[n]);
        }
    }
}

// ---------------- LIF recurrence: one thread per (b, c) neuron --------------
__global__ __launch_bounds__(256) void lif_kernel(
    const float* __restrict__ Wlif, const float* __restrict__ blif,
    const int* __restrict__ winsPtr, float* __restrict__ out)
{
    const int idx = blockIdx.x * 256 + threadIdx.x;   // = b*CH + c
    const float y0 = g_y3[idx];
    const float y1 = g_y3[BSZ * CH + idx];
    const float y2 = g_y3[2 * BSZ * CH + idx];
    const float w0 = Wlif[0], w1 = Wlif[1], w2 = Wlif[2];
    const float bl = blif[0];
    const int wins = *winsPtr;

    const int b = idx >> 12;          // /CH
    const int c = idx & (CH - 1);

    float m0 = 0.f, m1 = 0.f, m2 = 0.f, m3 = 0.f;
    float s0 = 0.f, s1 = 0.f, s2 = 0.f, s3 = 0.f;

    float* o = out + (size_t)b * wins * (CH * 4) + (size_t)c * 4;

    for (int t = 0; t < wins; t++) {
        // inner = mem[0:3] . Wlif + blif (fp32 fmuladd chain)
        float inner = __fadd_rn(
            __fmaf_rn(m2, w2, __fmaf_rn(m1, w1, __fmul_rn(m0, w0))), bl);
        // mem1 = mem * DECAY * (1 - spike) + input; (1-s) is exactly 0 or 1.
        m0 = __fadd_rn(__fmul_rn(__fmul_rn(m0, DECAY), 1.f - s0), y0);
        m1 = __fadd_rn(__fmul_rn(__fmul_rn(m1, DECAY), 1.f - s1), y1);
        m2 = __fadd_rn(__fmul_rn(__fmul_rn(m2, DECAY), 1.f - s2), y2);
        m3 = __fadd_rn(__fmul_rn(__fmul_rn(m3, DECAY), 1.f - s3), inner);
        s0 = (m0 > THRESH) ? 1.f : 0.f;
        s1 = (m1 > THRESH) ? 1.f : 0.f;
        s2 = (m2 > THRESH) ? 1.f : 0.f;
        s3 = (m3 > THRESH) ? 1.f : 0.f;
        *(float4*)(o + (size_t)t * CH * 4) = make_float4(s0, s1, s2, s3);
    }
}

// ---------------- launch ----------------------------------------------------
extern "C" void kernel_launch(void* const* d_in, const int* in_sizes, int n_in,
                              void* d_out, int out_size) {
    const float* x    = (const float*)d_in[0];
    const float* W1   = (const float*)d_in[1];
    const float* b1   = (const float*)d_in[2];
    const float* W2   = (const float*)d_in[3];
    const float* b2   = (const float*)d_in[4];
    const float* W3   = (const float*)d_in[5];
    const float* b3   = (const float*)d_in[6];
    const float* Wlif = (const float*)d_in[7];
    const float* blif = (const float*)d_in[8];
    const int*   wins = (const int*)d_in[9];

    dim3 ggrid(3 * CH / BN, BSZ / BM);   // (192, 2)
    gemm3_kernel<<<ggrid, 256>>>(x, W1, b1, W2, b2, W3, b3);
    lif_kernel<<<(BSZ * CH) / 256, 256>>>(Wlif, blif, wins, (float*)d_out);
}

// round 11
// speedup vs baseline: 1.1292x; 1.1292x over previous
#include <cuda_runtime.h>
#include <cstdint>

#define THRESH 0.8f
#define DECAY  0.2f

constexpr int BSZ = 256;   // batch
constexpr int CH  = 4096;  // out features
constexpr int KD  = 4096;  // in features

// Scratch: 3 planes [BSZ][CH] of fc outputs (x@Wj.T + bj), time-invariant.
__device__ float g_y3[3 * BSZ * CH];

typedef unsigned long long u64;

// ---- packed f32x2 helpers (Blackwell FFMA2 path; lane-wise exact fp32) ----
__device__ __forceinline__ u64 pack2(float lo, float hi) {
    u64 r; asm("mov.b64 %0, {%1, %2};" : "=l"(r) : "f"(lo), "f"(hi)); return r;
}
__device__ __forceinline__ void unpack2(u64 v, float& lo, float& hi) {
    asm("mov.b64 {%0, %1}, %2;" : "=f"(lo), "=f"(hi) : "l"(v));
}
__device__ __forceinline__ u64 fma2(u64 a, u64 b, u64 c) {
    u64 d; asm("fma.rn.f32x2 %0, %1, %2, %3;" : "=l"(d) : "l"(a), "l"(b), "l"(c));
    return d;
}
__device__ __forceinline__ u64 add2(u64 a, u64 b) {
    u64 d; asm("add.rn.f32x2 %0, %1, %2;" : "=l"(d) : "l"(a), "l"(b));
    return d;
}

// ---------------- GEMM: y[j][m][n] = sum_k x[m][k]*Wj[n][k] + bj[n] ----------
// Reference-exact order (verified rel_err==0.0): split-K=2 halves {0..2047},
// {2048..4095}; each half an ascending fused-FMA chain from zero; halves
// folded (p0+p1); bias added last. f32x2 packs two INDEPENDENT outputs
// (adjacent m rows) per instruction -- per-output arithmetic unchanged.
constexpr int BM = 128, BN = 64, BK = 16, TM = 8, TN = 4;  // 256 threads
constexpr int HALF_B = 2048;

__global__ __launch_bounds__(256, 2) void gemm3_kernel(
    const float* __restrict__ x,
    const float* __restrict__ W1, const float* __restrict__ b1,
    const float* __restrict__ W2, const float* __restrict__ b2,
    const float* __restrict__ W3, const float* __restrict__ b3)
{
    __shared__ float As[BK][BM];   // [k][m]
    __shared__ float Bs[BK][BN];   // [k][n]

    const int tid = threadIdx.x;
    const int bx  = blockIdx.x;    // 0 .. 191
    const int by  = blockIdx.y;    // 0 .. 1

    const int blocksPerJ = CH / BN;          // 64
    const int j  = bx / blocksPerJ;
    const int n0 = (bx % blocksPerJ) * BN;
    const int m0 = by * BM;

    const float* W    = (j == 0) ? W1 : (j == 1) ? W2 : W3;
    const float* bias = (j == 0) ? b1 : (j == 1) ? b2 : b3;

    const int tx = tid % (BN / TN);   // 16 -> n
    const int ty = tid / (BN / TN);   // 16 -> m

    // accumulators: 4 m-pairs x 4 n columns, packed (m even, m odd)
    u64 run2[TM / 2][TN];
    u64 tot2[TM / 2][TN];
    #pragma unroll
    for (int p = 0; p < TM / 2; p++)
        #pragma unroll
        for (int q = 0; q < TN; q++) { run2[p][q] = 0ULL; tot2[p][q] = 0ULL; }

    const int NKB = KD / BK;   // 256
    for (int kb = 0; kb < NKB; kb++) {
        const int k0 = kb * BK;
        // A tile: BM x BK = 512 float4, 2 per thread
        #pragma unroll
        for (int l = 0; l < 2; l++) {
            int li  = tid + l * 256;
            int row = li >> 2;
            int kq  = (li & 3) * 4;
            float4 v = *(const float4*)(x + (size_t)(m0 + row) * KD + k0 + kq);
            As[kq + 0][row] = v.x;
            As[kq + 1][row] = v.y;
            As[kq + 2][row] = v.z;
            As[kq + 3][row] = v.w;
        }
        // W tile: BN x BK = 256 float4, 1 per thread
        {
            int row = tid >> 2;
            int kq  = (tid & 3) * 4;
            float4 v = *(const float4*)(W + (size_t)(n0 + row) * KD + k0 + kq);
            Bs[kq + 0][row] = v.x;
            Bs[kq + 1][row] = v.y;
            Bs[kq + 2][row] = v.z;
            Bs[kq + 3][row] = v.w;
        }
        __syncthreads();

        #pragma unroll
        for (int kk = 0; kk < BK; kk++) {
            // A pairs: 8 consecutive m values -> 4 packed b64 (two LDS.128)
            ulonglong2 av01 = *(const ulonglong2*)(&As[kk][ty * TM]);
            ulonglong2 av23 = *(const ulonglong2*)(&As[kk][ty * TM + 4]);
            u64 av[4] = { av01.x, av01.y, av23.x, av23.y };
            // B: 4 consecutive n values, each replicated to both lanes
            float4 bv = *(const float4*)(&Bs[kk][tx * TN]);
            u64 bb[4] = { pack2(bv.x, bv.x), pack2(bv.y, bv.y),
                          pack2(bv.z, bv.z), pack2(bv.w, bv.w) };
            #pragma unroll
            for (int p = 0; p < TM / 2; p++)
                #pragma unroll
                for (int q = 0; q < TN; q++)
                    run2[p][q] = fma2(av[p], bb[q], run2[p][q]);
        }

        // fold at the split-K boundary and at the end (k0+16 == 2048 | 4096)
        if (k0 + BK == HALF_B || k0 + BK == KD) {
            #pragma unroll
            for (int p = 0; p < TM / 2; p++)
                #pragma unroll
                for (int q = 0; q < TN; q++) {
                    tot2[p][q] = add2(tot2[p][q], run2[p][q]);
                    run2[p][q] = 0ULL;
                }
        }
        __syncthreads();
    }

    float* yp = g_y3 + (size_t)j * BSZ * CH;
    #pragma unroll
    for (int p = 0; p < TM / 2; p++) {
        int m_lo = m0 + ty * TM + 2 * p;
        #pragma unroll
        for (int q = 0; q < TN; q++) {
            int n = n0 + tx * TN + q;
            float lo, hi;
            unpack2(tot2[p][q], lo, hi);
            yp[(size_t)m_lo * CH + n]       = __fadd_rn(lo, bias[n]);
            yp[(size_t)(m_lo + 1) * CH + n] = __fadd_rn(hi, bias[n]);
        }
    }
}

// ---------------- LIF recurrence: one thread per (b, c) neuron --------------
__global__ __launch_bounds__(256) void lif_kernel(
    const float* __restrict__ Wlif, const float* __restrict__ blif,
    const int* __restrict__ winsPtr, float* __restrict__ out)
{
    const int idx = blockIdx.x * 256 + threadIdx.x;   // = b*CH + c
    const float y0 = g_y3[idx];
    const float y1 = g_y3[BSZ * CH + idx];
    const float y2 = g_y3[2 * BSZ * CH + idx];
    const float w0 = Wlif[0], w1 = Wlif[1], w2 = Wlif[2];
    const float bl = blif[0];
    const int wins = *winsPtr;

    const int b = idx >> 12;          // /CH
    const int c = idx & (CH - 1);

    float m0 = 0.f, m1 = 0.f, m2 = 0.f, m3 = 0.f;
    float s0 = 0.f, s1 = 0.f, s2 = 0.f, s3 = 0.f;

    float* o = out + (size_t)b * wins * (CH * 4) + (size_t)c * 4;

    for (int t = 0; t < wins; t++) {
        float inner = __fadd_rn(
            __fmaf_rn(m2, w2, __fmaf_rn(m1, w1, __fmul_rn(m0, w0))), bl);
        m0 = __fadd_rn(__fmul_rn(__fmul_rn(m0, DECAY), 1.f - s0), y0);
        m1 = __fadd_rn(__fmul_rn(__fmul_rn(m1, DECAY), 1.f - s1), y1);
        m2 = __fadd_rn(__fmul_rn(__fmul_rn(m2, DECAY), 1.f - s2), y2);
        m3 = __fadd_rn(__fmul_rn(__fmul_rn(m3, DECAY), 1.f - s3), inner);
        s0 = (m0 > THRESH) ? 1.f : 0.f;
        s1 = (m1 > THRESH) ? 1.f : 0.f;
        s2 = (m2 > THRESH) ? 1.f : 0.f;
        s3 = (m3 > THRESH) ? 1.f : 0.f;
        *(float4*)(o + (size_t)t * CH * 4) = make_float4(s0, s1, s2, s3);
    }
}

// ---------------- launch ----------------------------------------------------
extern "C" void kernel_launch(void* const* d_in, const int* in_sizes, int n_in,
                              void* d_out, int out_size) {
    const float* x    = (const float*)d_in[0];
    const float* W1   = (const float*)d_in[1];
    const float* b1   = (const float*)d_in[2];
    const float* W2   = (const float*)d_in[3];
    const float* b2   = (const float*)d_in[4];
    const float* W3   = (const float*)d_in[5];
    const float* b3   = (const float*)d_in[6];
    const float* Wlif = (const float*)d_in[7];
    const float* blif = (const float*)d_in[8];
    const int*   wins = (const int*)d_in[9];

    dim3 ggrid(3 * CH / BN, BSZ / BM);   // (192, 2)
    gemm3_kernel<<<ggrid, 256>>>(x, W1, b1, W2, b2, W3, b3);
    lif_kernel<<<(BSZ * CH) / 256, 256>>>(Wlif, blif, wins, (float*)d_out);
}